// round 11
// baseline (speedup 1.0000x reference)
#include <cuda_runtime.h>
#include <cuda_bf16.h>
#include <math.h>
#include <float.h>

// Problem constants
#define NS      262144
#define KC      512
#define DEPTH   128          // 2*D
#define HALF_D  64
#define BM      128          // samples per block
#define BETA_C  0.25f
#define DECAY_C 0.99f
#define OMD_C   0.01f
#define EPS_C   1e-5f
#define MARGIN  1e-2f        // > 4*E where E bounds |screen - exact| (~2e-3)

// Output layout (float32, concatenated in reference return order)
static const size_t OFF_ZQR  = 0;               // N*D
static const size_t OFF_ZQI  = 16777216;        // N*D
static const size_t OFF_LOSS = 33554432;        // N
static const size_t OFF_IDX  = 33816576;        // N
static const size_t OFF_ENT  = 34078720;        // 1
static const size_t OFF_EMBW = 34078721;        // K*2D
static const size_t OFF_CLUS = 34144257;        // K
static const size_t OFF_EMAW = 34144769;        // K*2D

// Scratch (device globals; no allocation allowed)
__device__ __align__(16) float g_dw[KC * DEPTH];
__device__ float g_ntotal[KC];
__device__ float g_ysq[KC];
__device__ float g_cs[KC];
__device__ __align__(16) __nv_bfloat16 g_emb16[KC * DEPTH];   // bf16 copy of emb

// ---------------- kernel 1: zero scratch + y_sq[k] + bf16 emb -------------
// ysq accumulation order unchanged from R7 (bitwise load-bearing).
__global__ void k_prep(const float* __restrict__ emb) {
    int gt   = blockIdx.x * blockDim.x + threadIdx.x;
    int row  = gt >> 5;
    int lane = gt & 31;
    if (row >= KC) return;
    float s = 0.0f;
    #pragma unroll
    for (int j = lane; j < DEPTH; j += 32) {
        float v = emb[(size_t)row * DEPTH + j];
        s = __fadd_rn(s, __fmul_rn(v, v));
        g_dw[(size_t)row * DEPTH + j] = 0.0f;
        g_emb16[(size_t)row * DEPTH + j] = __float2bfloat16(v);  // RN
    }
    #pragma unroll
    for (int o = 16; o > 0; o >>= 1)
        s = __fadd_rn(s, __shfl_down_sync(0xffffffffu, s, o));
    if (lane == 0) {
        g_ysq[row]    = s;
        g_ntotal[row] = 0.0f;
    }
}

// ---------------- kernel 2: main fused screen-GEMM + exact rescore --------
// smem (floats):
#define Z_OFF    0            // z fp32 [128 samples][132]        16896
#define S_OFF    16896        // S chunk fp32 [128][132]          16896
#define AF_OFF   33792        // A frags, 8192 uint32
#define BF_OFF   41984        // B frags (per chunk), 8192 uint32
#define YS_OFF   50176        // ysq fp32 [512]
#define XS_OFF   50688        // x_sq [128]
#define SMIN_OFF 50816        // running screen min [128]
#define BIDX_OFF 50944        // winner idx [128] (int)
#define SMEM_FLOATS 51072
#define SMEM_BYTES  (SMEM_FLOATS * 4)

__device__ __forceinline__ void hmma16816(float& d0, float& d1, float& d2, float& d3,
                                          unsigned a0, unsigned a1, unsigned a2, unsigned a3,
                                          unsigned b0, unsigned b1) {
    asm volatile(
        "mma.sync.aligned.m16n8k16.row.col.f32.bf16.bf16.f32 "
        "{%0,%1,%2,%3}, {%4,%5,%6,%7}, {%8,%9}, {%0,%1,%2,%3};"
        : "+f"(d0), "+f"(d1), "+f"(d2), "+f"(d3)
        : "r"(a0), "r"(a1), "r"(a2), "r"(a3), "r"(b0), "r"(b1));
}

__device__ __forceinline__ unsigned pack_bf16x2(float lo, float hi) {
    unsigned r;
    asm("cvt.rn.bf16x2.f32 %0, %1, %2;" : "=r"(r) : "f"(hi), "f"(lo));
    return r;
}

__global__ __launch_bounds__(256, 1)
void k_main(const float* __restrict__ zr, const float* __restrict__ zi,
            const float* __restrict__ emb, float* __restrict__ out) {
    extern __shared__ float sm[];
    float*    Z    = sm + Z_OFF;       // stride 132 floats, sample-major
    float*    S    = sm + S_OFF;       // stride 132
    unsigned* AF   = (unsigned*)(sm + AF_OFF);
    unsigned* BF   = (unsigned*)(sm + BF_OFF);
    float*    YS   = sm + YS_OFF;
    float*    XS   = sm + XS_OFF;
    float*    SMIN = sm + SMIN_OFF;
    int*      BIDX = (int*)(sm + BIDX_OFF);

    const int tid  = threadIdx.x;
    const int w    = tid >> 5;       // warp id = m-tile id (16 samples each)
    const int lane = tid & 31;
    const int row0 = blockIdx.x * BM;

    // --- load z tile sample-major: Z[m][0..63]=zr, Z[m][64..127]=zi ---
    for (int e = tid; e < BM * 16; e += 256) {
        int m = e >> 4, q = e & 15;
        float4 v = ((const float4*)zr)[(size_t)(row0 + m) * 16 + q];
        *(float4*)&Z[m * 132 + 4 * q] = v;
    }
    for (int e = tid; e < BM * 16; e += 256) {
        int m = e >> 4, q = e & 15;
        float4 v = ((const float4*)zi)[(size_t)(row0 + m) * 16 + q];
        *(float4*)&Z[m * 132 + 64 + 4 * q] = v;
    }
    // ysq
    for (int e = tid; e < KC; e += 256) YS[e] = g_ysq[e];
    __syncthreads();

    // --- x_sq: strictly sequential k=0..127 (bitwise load-bearing) ---
    if (tid < BM) {
        float s = 0.0f;
        for (int k = 0; k < DEPTH; k++) {
            float v = Z[tid * 132 + k];
            s = __fadd_rn(s, __fmul_rn(v, v));
        }
        XS[tid] = s;
        SMIN[tid] = FLT_MAX;
    }

    // --- build A fragments (PTX m16n8k16 bf16 mapping), once per CTA ---
    // word (m, kw) holds z bf16 pair (k=2kw, 2kw+1)
    for (int e = tid; e < BM * 64; e += 256) {
        int m = e >> 6, kw = e & 63;
        float2 zp = *(const float2*)&Z[m * 132 + 2 * kw];
        unsigned word = pack_bf16x2(zp.x, zp.y);
        int mt = m >> 4, r = m & 15;
        int ks = kw >> 3;
        int fl_ = ((m & 7) << 2) | (kw & 3);
        int reg = ((r >> 3) & 1) | ((kw & 4) ? 2 : 0);
        AF[(((mt << 3) + ks) << 5 | fl_) * 4 + reg] = word;
    }
    __syncthreads();

    // preload this warp's A regs: conflict-free LDS.128
    unsigned a[8][4];
    #pragma unroll
    for (int ks = 0; ks < 8; ks++) {
        uint4 v = *(const uint4*)&AF[(((w << 3) + ks) << 5 | lane) * 4];
        a[ks][0] = v.x; a[ks][1] = v.y; a[ks][2] = v.z; a[ks][3] = v.w;
    }

    // per-sample winner state (threads 0..127)
    float bv = FLT_MAX;
    int   bi = 0x7fffffff;

    const unsigned* emb16w = (const unsigned*)g_emb16;   // word (n*64 + kw)
    const int gid  = lane >> 2;    // groupID
    const int tig  = lane & 3;     // threadID_in_group

    for (int c = 0; c < 4; c++) {
        __syncthreads();   // S/BF free from previous chunk
        // --- fill B fragments for codewords n = c*128 .. c*128+127 ---
        for (int e = tid; e < 128 * 64; e += 256) {
            int nl = e >> 6, kw = e & 63;
            unsigned word = emb16w[(size_t)(c * 128 + nl) * 64 + kw];
            int nt = nl >> 3;
            int ks = kw >> 3;
            int fl_ = ((nl & 7) << 2) | (kw & 3);
            int reg = (kw & 4) ? 1 : 0;
            BF[(((nt << 3) + ks) << 5 | fl_) * 2 + reg] = word;
        }
        __syncthreads();

        // --- screening GEMM: 16 n-tiles x 8 k-steps of m16n8k16 ---
        #pragma unroll 1
        for (int nt = 0; nt < 16; nt++) {
            float d0 = 0.f, d1 = 0.f, d2 = 0.f, d3 = 0.f;
            #pragma unroll
            for (int ks = 0; ks < 8; ks++) {
                uint2 b = *(const uint2*)&BF[(((nt << 3) + ks) << 5 | lane) * 2];
                hmma16816(d0, d1, d2, d3,
                          a[ks][0], a[ks][1], a[ks][2], a[ks][3], b.x, b.y);
            }
            // screened score s' = ys - 2*dot (x_sq offset common per sample)
            int nl = (nt << 3) + (tig << 1);
            int nn = (c << 7) + nl;
            float2 s0, s1;
            s0.x = __fmaf_rn(-2.f, d0, YS[nn]);
            s0.y = __fmaf_rn(-2.f, d1, YS[nn + 1]);
            s1.x = __fmaf_rn(-2.f, d2, YS[nn]);
            s1.y = __fmaf_rn(-2.f, d3, YS[nn + 1]);
            int m0 = (w << 4) + gid;
            *(float2*)&S[m0 * 132 + nl]       = s0;
            *(float2*)&S[(m0 + 8) * 132 + nl] = s1;
        }
        __syncthreads();

        // --- scan + exact rescore (thread m < 128 handles sample m) ---
        if (tid < BM) {
            const int m = tid;
            float rm = SMIN[m];
            for (int jl = 0; jl < 128; jl++)
                rm = fminf(rm, S[m * 132 + jl]);
            SMIN[m] = rm;
            float thresh = rm + MARGIN;
            for (int jl = 0; jl < 128; jl++) {
                if (S[m * 132 + jl] <= thresh) {
                    int j = (c << 7) + jl;
                    // exact sequential-k fp32 FMA chain (bitwise = reference)
                    float dot = 0.0f;
                    const float4* er = (const float4*)(emb + (size_t)j * DEPTH);
                    #pragma unroll 8
                    for (int q = 0; q < 32; q++) {
                        float4 e4 = er[q];
                        float4 z4 = *(const float4*)&Z[m * 132 + 4 * q];
                        dot = __fmaf_rn(z4.x, e4.x, dot);
                        dot = __fmaf_rn(z4.y, e4.y, dot);
                        dot = __fmaf_rn(z4.z, e4.z, dot);
                        dot = __fmaf_rn(z4.w, e4.w, dot);
                    }
                    float t0 = __fadd_rn(XS[m], YS[j]);
                    float s  = __fadd_rn(t0, __fmul_rn(-2.0f, dot));
                    if (s < bv || (s == bv && j < bi)) { bv = s; bi = j; }
                }
            }
        }
    }

    // --- winner outputs ---
    if (tid < BM) {
        BIDX[tid] = bi;
        out[OFF_IDX + row0 + tid]  = (float)bi;
        out[OFF_LOSS + row0 + tid] = __fmul_rn(BETA_C, __fmul_rn(bv, (1.0f / 128.0f)));
        atomicAdd(&g_ntotal[bi], 1.0f);
    }
    __syncthreads();

    // --- zq gather + straight-through write + dw vector segment-sum ---
    for (int e = tid; e < BM * 32; e += 256) {
        int m = e >> 5;
        int d = (e & 31) * 4;
        float4 zv = *(const float4*)&Z[m * 132 + d];
        int ix = BIDX[m];
        float4 qv = *(const float4*)&emb[(size_t)ix * DEPTH + d];
        float4 o;   // reference: z + fl(q - z), each op rounded once
        o.x = __fadd_rn(zv.x, __fsub_rn(qv.x, zv.x));
        o.y = __fadd_rn(zv.y, __fsub_rn(qv.y, zv.y));
        o.z = __fadd_rn(zv.z, __fsub_rn(qv.z, zv.z));
        o.w = __fadd_rn(zv.w, __fsub_rn(qv.w, zv.w));
        size_t gi = (size_t)(row0 + m);
        if (d < HALF_D)
            *(float4*)&out[OFF_ZQR + gi * HALF_D + d] = o;
        else
            *(float4*)&out[OFF_ZQI + gi * HALF_D + (d - HALF_D)] = o;
        atomicAdd((float4*)&g_dw[ix * DEPTH + d], zv);
    }
}

// ---------------- kernel 3a: cluster EMA, tot, entropy ----------------
__global__ void k_final_a(const float* __restrict__ ecs, float* __restrict__ out) {
    __shared__ float red[KC];
    __shared__ float red2[KC];
    int t = threadIdx.x;
    float nt = g_ntotal[t];
    float nc = __fadd_rn(__fmul_rn(ecs[t], DECAY_C), __fmul_rn(OMD_C, nt));
    float p  = __fmul_rn(nt, (1.0f / (float)NS));
    red[t]  = nc;
    red2[t] = -__fmul_rn(p, logf(__fadd_rn(p, 1e-10f)));
    __syncthreads();
    for (int s = KC / 2; s > 0; s >>= 1) {
        if (t < s) { red[t] += red[t + s]; red2[t] += red2[t + s]; }
        __syncthreads();
    }
    float tot = red[0];
    out[OFF_CLUS + t] = nc;
    g_cs[t] = __fmul_rn(__fdiv_rn(__fadd_rn(nc, EPS_C),
                                  __fadd_rn(tot, __fmul_rn((float)KC, EPS_C))), tot);
    if (t == 0) out[OFF_ENT] = __fdiv_rn(red2[0], logf(512.0f));
}

// ---------------- kernel 3b: ema_w / emb_w update ----------------
__global__ void k_final_b(const float* __restrict__ emaw, float* __restrict__ out) {
    int e = blockIdx.x * blockDim.x + threadIdx.x;   // 65536 threads
    int k = e >> 7;
    float ew = __fadd_rn(__fmul_rn(emaw[e], DECAY_C), __fmul_rn(OMD_C, g_dw[e]));
    out[OFF_EMAW + e] = ew;
    out[OFF_EMBW + e] = __fdiv_rn(ew, g_cs[k]);
}

// ---------------- launch ----------------
extern "C" void kernel_launch(void* const* d_in, const int* in_sizes, int n_in,
                              void* d_out, int out_size) {
    const float* zr   = (const float*)d_in[0];
    const float* zi   = (const float*)d_in[1];
    const float* emb  = (const float*)d_in[2];
    const float* ecs  = (const float*)d_in[3];
    const float* emaw = (const float*)d_in[4];
    float* out = (float*)d_out;

    cudaFuncSetAttribute(k_main, cudaFuncAttributeMaxDynamicSharedMemorySize, SMEM_BYTES);

    k_prep<<<64, 256>>>(emb);
    k_main<<<NS / BM, 256, SMEM_BYTES>>>(zr, zi, emb, out);
    k_final_a<<<1, KC>>>(ecs, out);
    k_final_b<<<KC * DEPTH / 256, 256>>>(emaw, out);
}

// round 16
// speedup vs baseline: 4.3040x; 4.3040x over previous
#include <cuda_runtime.h>
#include <cuda_bf16.h>
#include <math.h>
#include <float.h>

// Problem constants
#define NS      262144
#define KC      512
#define DEPTH   128          // 2*D
#define HALF_D  64
#define BM      128          // samples per block
#define BETA_C  0.25f
#define DECAY_C 0.99f
#define OMD_C   0.01f
#define EPS_C   1e-5f
// |bf16_screen - exact| < 4e-3 worst case (2*1.6e-3 dot err + bf16 storage);
// 6e-3 margin provably keeps every possible exact winner in the candidate set.
#define MARGIN  6e-3f
#define CAND_CAP 256          // per-warp candidate cap (expect ~40)

// Output layout (float32, concatenated in reference return order)
static const size_t OFF_ZQR  = 0;               // N*D
static const size_t OFF_ZQI  = 16777216;        // N*D
static const size_t OFF_LOSS = 33554432;        // N
static const size_t OFF_IDX  = 33816576;        // N
static const size_t OFF_ENT  = 34078720;        // 1
static const size_t OFF_EMBW = 34078721;        // K*2D
static const size_t OFF_CLUS = 34144257;        // K
static const size_t OFF_EMAW = 34144769;        // K*2D

// Scratch (device globals; no allocation allowed)
__device__ __align__(16) float g_dw[KC * DEPTH];
__device__ float g_ntotal[KC];
__device__ float g_ysq[KC];
__device__ float g_cs[KC];
__device__ __align__(16) __nv_bfloat16 g_emb16[KC * DEPTH];   // bf16 copy of emb

// ---------------- kernel 1: zero scratch + y_sq[k] + bf16 emb -------------
__global__ void k_prep(const float* __restrict__ emb) {
    int gt   = blockIdx.x * blockDim.x + threadIdx.x;
    int row  = gt >> 5;
    int lane = gt & 31;
    if (row >= KC) return;
    float s = 0.0f;
    #pragma unroll
    for (int j = lane; j < DEPTH; j += 32) {
        float v = emb[(size_t)row * DEPTH + j];
        s = __fadd_rn(s, __fmul_rn(v, v));
        g_dw[(size_t)row * DEPTH + j] = 0.0f;
        g_emb16[(size_t)row * DEPTH + j] = __float2bfloat16(v);  // RN
    }
    #pragma unroll
    for (int o = 16; o > 0; o >>= 1)
        s = __fadd_rn(s, __shfl_down_sync(0xffffffffu, s, o));
    if (lane == 0) {
        g_ysq[row]    = s;
        g_ntotal[row] = 0.0f;
    }
}

// ---------------- kernel 2: screen-GEMM + reg-min + parallel rescore ------
// smem (float indices):
#define Z_OFF    0            // z fp32 [128][132]                16896
#define YS_OFF   16896        // ysq [512]
#define XS_OFF   17408        // x_sq [128]
#define SMIN_OFF 17536        // per-sample screened min [128]; reused as BIDX
#define KEY_OFF  17664        // 128 x ull winner keys (256 floats)
#define CNT_OFF  17920        // 8 ints
#define CAND_OFF 17928        // 8*256 uint
#define BF_OFF   19984        // 4096 words (64-codeword B frags)
#define S16_OFF  24080        // bf16 scores [128 samples][258 words]; AF aliases here
#define SMEM_FLOATS 57104
#define SMEM_BYTES  (SMEM_FLOATS * 4)

__device__ __forceinline__ void hmma16816(float& d0, float& d1, float& d2, float& d3,
                                          unsigned a0, unsigned a1, unsigned a2, unsigned a3,
                                          unsigned b0, unsigned b1) {
    asm volatile(
        "mma.sync.aligned.m16n8k16.row.col.f32.bf16.bf16.f32 "
        "{%0,%1,%2,%3}, {%4,%5,%6,%7}, {%8,%9}, {%0,%1,%2,%3};"
        : "+f"(d0), "+f"(d1), "+f"(d2), "+f"(d3)
        : "r"(a0), "r"(a1), "r"(a2), "r"(a3), "r"(b0), "r"(b1));
}

__device__ __forceinline__ unsigned pack_bf16x2(float lo, float hi) {
    unsigned r;
    asm("cvt.rn.bf16x2.f32 %0, %1, %2;" : "=r"(r) : "f"(hi), "f"(lo));
    return r;
}

__global__ __launch_bounds__(256, 1)
void k_main(const float* __restrict__ zr, const float* __restrict__ zi,
            const float* __restrict__ emb, float* __restrict__ out) {
    extern __shared__ float sm[];
    float*              Z    = sm + Z_OFF;       // stride 132, sample-major
    float*              YS   = sm + YS_OFF;
    float*              XS   = sm + XS_OFF;
    float*              SMIN = sm + SMIN_OFF;
    unsigned long long* KEY  = (unsigned long long*)(sm + KEY_OFF);
    int*                CNT  = (int*)(sm + CNT_OFF);
    unsigned*           CAND = (unsigned*)(sm + CAND_OFF);
    unsigned*           BF   = (unsigned*)(sm + BF_OFF);
    unsigned*           S16w = (unsigned*)(sm + S16_OFF);   // word view, stride 258
    unsigned*           AF   = (unsigned*)(sm + S16_OFF);   // aliased (used pre-loop only)

    const int tid  = threadIdx.x;
    const int w    = tid >> 5;       // warp id = m-tile id (16 samples each)
    const int lane = tid & 31;
    const int row0 = blockIdx.x * BM;

    // --- load z tile sample-major ---
    for (int e = tid; e < BM * 16; e += 256) {
        int m = e >> 4, q = e & 15;
        float4 v = ((const float4*)zr)[(size_t)(row0 + m) * 16 + q];
        *(float4*)&Z[m * 132 + 4 * q] = v;
    }
    for (int e = tid; e < BM * 16; e += 256) {
        int m = e >> 4, q = e & 15;
        float4 v = ((const float4*)zi)[(size_t)(row0 + m) * 16 + q];
        *(float4*)&Z[m * 132 + 64 + 4 * q] = v;
    }
    for (int e = tid; e < KC; e += 256) YS[e] = g_ysq[e];
    if (tid < BM) KEY[tid] = 0xFFFFFFFFFFFFFFFFull;
    if (tid < 8)  CNT[tid] = 0;
    __syncthreads();

    // --- x_sq: strictly sequential k=0..127 (bitwise load-bearing) ---
    if (tid < BM) {
        float s = 0.0f;
        for (int k = 0; k < DEPTH; k++) {
            float v = Z[tid * 132 + k];
            s = __fadd_rn(s, __fmul_rn(v, v));
        }
        XS[tid] = s;
    }

    // --- build A fragments (m16n8k16 bf16 mapping), consumed pre-loop ---
    for (int e = tid; e < BM * 64; e += 256) {
        int m = e >> 6, kw = e & 63;
        float2 zp = *(const float2*)&Z[m * 132 + 2 * kw];
        unsigned word = pack_bf16x2(zp.x, zp.y);
        int mt = m >> 4, r = m & 15;
        int ks = kw >> 3;
        int fl_ = ((m & 7) << 2) | (kw & 3);
        int reg = ((r >> 3) & 1) | ((kw & 4) ? 2 : 0);
        AF[(((mt << 3) + ks) << 5 | fl_) * 4 + reg] = word;
    }
    __syncthreads();

    unsigned a[8][4];
    #pragma unroll
    for (int ks = 0; ks < 8; ks++) {
        uint4 v = *(const uint4*)&AF[(((w << 3) + ks) << 5 | lane) * 4];
        a[ks][0] = v.x; a[ks][1] = v.y; a[ks][2] = v.z; a[ks][3] = v.w;
    }

    const unsigned* emb16w = (const unsigned*)g_emb16;
    const int gid = lane >> 2;     // groupID (row within tile)
    const int tig = lane & 3;      // thread in group (col pair)
    const int m0  = (w << 4) + gid;

    float rmin0 = FLT_MAX, rmin1 = FLT_MAX;   // per-thread running screen mins

    for (int c = 0; c < 4; c++) {
        for (int h = 0; h < 2; h++) {
            __syncthreads();   // BF free (prev GEMM done), AF dead after preload
            // fill B fragments for 64 codewords: n = c*128 + h*64 + nl
            for (int e = tid; e < 64 * 64; e += 256) {
                int nl = e >> 6, kw = e & 63;
                unsigned word = emb16w[(size_t)(c * 128 + h * 64 + nl) * 64 + kw];
                int nt = nl >> 3;
                int ks = kw >> 3;
                int fl_ = ((nl & 7) << 2) | (kw & 3);
                int reg = (kw & 4) ? 1 : 0;
                BF[(((nt << 3) + ks) << 5 | fl_) * 2 + reg] = word;
            }
            __syncthreads();

            #pragma unroll 1
            for (int nt = 0; nt < 8; nt++) {
                float d0 = 0.f, d1 = 0.f, d2 = 0.f, d3 = 0.f;
                #pragma unroll
                for (int ks = 0; ks < 8; ks++) {
                    uint2 b = *(const uint2*)&BF[(((nt << 3) + ks) << 5 | lane) * 2];
                    hmma16816(d0, d1, d2, d3,
                              a[ks][0], a[ks][1], a[ks][2], a[ks][3], b.x, b.y);
                }
                // screened score s' = ys - 2*dot (x_sq common offset dropped)
                int colw = c * 64 + h * 32 + nt * 4 + tig;   // word column = j>>1
                int nn   = colw * 2;
                float s0x = __fmaf_rn(-2.f, d0, YS[nn]);
                float s0y = __fmaf_rn(-2.f, d1, YS[nn + 1]);
                float s1x = __fmaf_rn(-2.f, d2, YS[nn]);
                float s1y = __fmaf_rn(-2.f, d3, YS[nn + 1]);
                rmin0 = fminf(rmin0, fminf(s0x, s0y));
                rmin1 = fminf(rmin1, fminf(s1x, s1y));
                S16w[m0 * 258 + colw]       = pack_bf16x2(s0x, s0y);
                S16w[(m0 + 8) * 258 + colw] = pack_bf16x2(s1x, s1y);
            }
        }
    }

    // --- per-sample screened min: reduce across the 4-thread tig group ---
    rmin0 = fminf(rmin0, __shfl_xor_sync(0xffffffffu, rmin0, 1));
    rmin0 = fminf(rmin0, __shfl_xor_sync(0xffffffffu, rmin0, 2));
    rmin1 = fminf(rmin1, __shfl_xor_sync(0xffffffffu, rmin1, 1));
    rmin1 = fminf(rmin1, __shfl_xor_sync(0xffffffffu, rmin1, 2));
    if (tig == 0) { SMIN[m0] = rmin0; SMIN[m0 + 8] = rmin1; }
    __syncthreads();

    // --- extraction: warp w scans its 16 samples, 32 lanes parallel.
    //     512 scores = 256 WORDS per sample -> i in [0,8) x 32 lanes. ---
    for (int t = 0; t < 16; t++) {
        int s = (w << 4) + t;
        float thresh = SMIN[s] + MARGIN;
        #pragma unroll
        for (int i = 0; i < 8; i++) {
            unsigned word = S16w[s * 258 + i * 32 + lane];
            float f0 = __uint_as_float(word << 16);
            float f1 = __uint_as_float(word & 0xFFFF0000u);
            int j0 = (i * 32 + lane) * 2;
            if (f0 <= thresh) {
                int pos = atomicAdd(&CNT[w], 1);
                if (pos < CAND_CAP) CAND[w * CAND_CAP + pos] = (unsigned)(s << 16 | j0);
            }
            if (f1 <= thresh) {
                int pos = atomicAdd(&CNT[w], 1);
                if (pos < CAND_CAP) CAND[w * CAND_CAP + pos] = (unsigned)(s << 16 | (j0 + 1));
            }
        }
    }
    __syncwarp();

    // --- warp-parallel exact rescore: one candidate per LANE, no divergence ---
    int cnt = CNT[w];
    if (cnt > CAND_CAP) cnt = CAND_CAP;
    for (int base = 0; base < cnt; base += 32) {
        int e = base + lane;
        bool valid = e < cnt;
        unsigned ent = valid ? CAND[w * CAND_CAP + e] : 0u;
        int m = ent >> 16;
        int j = ent & 0xFFFF;
        // exact sequential-k fp32 FMA chain (bitwise = reference)
        float dot = 0.0f;
        const float4* er = (const float4*)(emb + (size_t)j * DEPTH);
        #pragma unroll 8
        for (int q = 0; q < 32; q++) {
            float4 e4 = er[q];
            float4 z4 = *(const float4*)&Z[m * 132 + 4 * q];
            dot = __fmaf_rn(z4.x, e4.x, dot);
            dot = __fmaf_rn(z4.y, e4.y, dot);
            dot = __fmaf_rn(z4.z, e4.z, dot);
            dot = __fmaf_rn(z4.w, e4.w, dot);
        }
        float t0 = __fadd_rn(XS[m], YS[j]);
        float s  = __fadd_rn(t0, __fmul_rn(-2.0f, dot));
        if (valid) {
            // positive-float bit order; low index wins ties = first-min argmin
            unsigned long long key = ((unsigned long long)__float_as_uint(s) << 32)
                                   | (unsigned long long)j;
            atomicMin(&KEY[m], key);
        }
    }
    __syncthreads();

    // --- winner outputs (SMIN reused as BIDX) ---
    int* BIDX = (int*)SMIN;
    if (tid < BM) {
        unsigned long long key = KEY[tid];
        int   bi = (int)(key & 0xFFFFFFFFull);
        float bv = __uint_as_float((unsigned)(key >> 32));
        BIDX[tid] = bi;
        out[OFF_IDX + row0 + tid]  = (float)bi;
        out[OFF_LOSS + row0 + tid] = __fmul_rn(BETA_C, __fmul_rn(bv, (1.0f / 128.0f)));
        atomicAdd(&g_ntotal[bi], 1.0f);
    }
    __syncthreads();

    // --- zq gather + straight-through write + dw vector segment-sum ---
    for (int e = tid; e < BM * 32; e += 256) {
        int m = e >> 5;
        int d = (e & 31) * 4;
        float4 zv = *(const float4*)&Z[m * 132 + d];
        int ix = BIDX[m];
        float4 qv = *(const float4*)&emb[(size_t)ix * DEPTH + d];
        float4 o;   // reference: z + fl(q - z), each op rounded once
        o.x = __fadd_rn(zv.x, __fsub_rn(qv.x, zv.x));
        o.y = __fadd_rn(zv.y, __fsub_rn(qv.y, zv.y));
        o.z = __fadd_rn(zv.z, __fsub_rn(qv.z, zv.z));
        o.w = __fadd_rn(zv.w, __fsub_rn(qv.w, zv.w));
        size_t gi = (size_t)(row0 + m);
        if (d < HALF_D)
            *(float4*)&out[OFF_ZQR + gi * HALF_D + d] = o;
        else
            *(float4*)&out[OFF_ZQI + gi * HALF_D + (d - HALF_D)] = o;
        atomicAdd((float4*)&g_dw[ix * DEPTH + d], zv);
    }
}

// ---------------- kernel 3a: cluster EMA, tot, entropy ----------------
__global__ void k_final_a(const float* __restrict__ ecs, float* __restrict__ out) {
    __shared__ float red[KC];
    __shared__ float red2[KC];
    int t = threadIdx.x;
    float nt = g_ntotal[t];
    float nc = __fadd_rn(__fmul_rn(ecs[t], DECAY_C), __fmul_rn(OMD_C, nt));
    float p  = __fmul_rn(nt, (1.0f / (float)NS));
    red[t]  = nc;
    red2[t] = -__fmul_rn(p, logf(__fadd_rn(p, 1e-10f)));
    __syncthreads();
    for (int s = KC / 2; s > 0; s >>= 1) {
        if (t < s) { red[t] += red[t + s]; red2[t] += red2[t + s]; }
        __syncthreads();
    }
    float tot = red[0];
    out[OFF_CLUS + t] = nc;
    g_cs[t] = __fmul_rn(__fdiv_rn(__fadd_rn(nc, EPS_C),
                                  __fadd_rn(tot, __fmul_rn((float)KC, EPS_C))), tot);
    if (t == 0) out[OFF_ENT] = __fdiv_rn(red2[0], logf(512.0f));
}

// ---------------- kernel 3b: ema_w / emb_w update ----------------
__global__ void k_final_b(const float* __restrict__ emaw, float* __restrict__ out) {
    int e = blockIdx.x * blockDim.x + threadIdx.x;   // 65536 threads
    int k = e >> 7;
    float ew = __fadd_rn(__fmul_rn(emaw[e], DECAY_C), __fmul_rn(OMD_C, g_dw[e]));
    out[OFF_EMAW + e] = ew;
    out[OFF_EMBW + e] = __fdiv_rn(ew, g_cs[k]);
}

// ---------------- launch ----------------
extern "C" void kernel_launch(void* const* d_in, const int* in_sizes, int n_in,
                              void* d_out, int out_size) {
    const float* zr   = (const float*)d_in[0];
    const float* zi   = (const float*)d_in[1];
    const float* emb  = (const float*)d_in[2];
    const float* ecs  = (const float*)d_in[3];
    const float* emaw = (const float*)d_in[4];
    float* out = (float*)d_out;

    cudaFuncSetAttribute(k_main, cudaFuncAttributeMaxDynamicSharedMemorySize, SMEM_BYTES);

    k_prep<<<64, 256>>>(emb);
    k_main<<<NS / BM, 256, SMEM_BYTES>>>(zr, zi, emb, out);
    k_final_a<<<1, KC>>>(ecs, out);
    k_final_b<<<KC * DEPTH / 256, 256>>>(emaw, out);
}